// round 9
// baseline (speedup 1.0000x reference)
#include <cuda_runtime.h>
#include <cstddef>

// Problem constants (dataset: B=2, N=50000, D=16)
#define MAXB 2
#define MAXN 50000

// Packed coordinates: g_pack[2t] = {x1,y1,z1,0}, g_pack[2t+1] = {x2,y2,z2,0}.
// 32B-aligned pair -> both float4 gathers for one neighbor hit ONE 32B sector.
__device__ float4 g_pack[2 * MAXB * MAXN];

// FMA-pipe inverse sqrt (no MUFU). 2 Newton steps: rel err ~5e-6.
__device__ __forceinline__ float frsqrt_fast(float x) {
    float xh = 0.5f * x;
    float y = __int_as_float(0x5f3759df - (__float_as_int(x) >> 1));
    y = y * (1.5f - xh * y * y);
    y = y * (1.5f - xh * y * y);
    return y;
}

// ---------------------------------------------------------------------------
// Kernel 1: float3 AoS -> interleaved float4 pairs.
// Thread t handles point t: lane-stride-3 scalar loads (coalesced sectors),
// lane-stride-32B float4 stores (8 lines per STG wavefront batch). This was
// measured cheap (total-main = 1.7us in R2); do NOT per-thread-vectorize it.
// ---------------------------------------------------------------------------
__global__ void pack_kernel(const float* __restrict__ xyz1,
                            const float* __restrict__ xyz2, int npts) {
    int t = blockIdx.x * blockDim.x + threadIdx.x;
    if (t >= npts) return;
    float ax = xyz1[3 * t + 0], ay = xyz1[3 * t + 1], az = xyz1[3 * t + 2];
    float cx = xyz2[3 * t + 0], cy = xyz2[3 * t + 1], cz = xyz2[3 * t + 2];
    g_pack[2 * t + 0] = make_float4(ax, ay, az, 0.f);
    g_pack[2 * t + 1] = make_float4(cx, cy, cz, 0.f);
}

// ---------------------------------------------------------------------------
// Exact Givens Jacobi rotation (FMA-pipe only): zeroes K[p][q].
// ---------------------------------------------------------------------------
template <int p, int q>
__device__ __forceinline__ void jrot(float K[3][3], float V[3][3]) {
    constexpr int r3 = 3 - p - q;
    float apq = K[p][q];
    float ad = K[p][p] - K[q][q];
    float b2 = 2.f * apq;
    float rsq = fmaf(ad, ad, b2 * b2) + 1e-30f;
    float w = frsqrt_fast(rsq);
    float r = rsq * w;  // sqrt(rsq)
    float u = r + fabsf(ad);
    float kk = frsqrt_fast(2.f * r * u);
    float c0 = u * kk;
    float s0 = b2 * kk;
    float c, s;
    if (ad >= 0.f) { c = c0; s = s0; }
    else           { c = fabsf(s0); s = copysignf(c0, b2); }

    float kpp = K[p][p], kqq = K[q][q], kpr = K[p][r3], kqr = K[q][r3];
    float cc = c * c, ss = s * s, cs = c * s;
    K[p][p] = cc * kpp + 2.f * cs * apq + ss * kqq;
    K[q][q] = ss * kpp - 2.f * cs * apq + cc * kqq;
    float npq = cs * (kqq - kpp) + (cc - ss) * apq;
    K[p][q] = npq; K[q][p] = npq;
    float npr = fmaf(c, kpr, s * kqr);
    float nqr = fmaf(-s, kpr, c * kqr);
    K[p][r3] = npr; K[r3][p] = npr;
    K[q][r3] = nqr; K[r3][q] = nqr;

#pragma unroll
    for (int i2 = 0; i2 < 3; i2++) {
        float vp = V[i2][p], vq = V[i2][q];
        V[i2][p] = fmaf(c, vp, s * vq);
        V[i2][q] = fmaf(-s, vp, c * vq);
    }
}

// ---------------------------------------------------------------------------
// Kernel 2 (fused): 2 threads per (batch, vertex). Each thread gathers 8
// neighbors (16 front-batched LDG.128 for high MLP), one-hop butterfly
// reduction, then both lanes redundantly run the 3x3 Procrustes solve
// (2x issue redundancy only) and split the 9-float store between them.
// ---------------------------------------------------------------------------
__global__ __launch_bounds__(256) void arap_fused_kernel(
    const int* __restrict__ nbr, const int* __restrict__ numN,
    const int* __restrict__ accN, const float* __restrict__ wgt,
    float* __restrict__ out, int n) {
    int t = blockIdx.x * blockDim.x + threadIdx.x;
    int v = t >> 1;
    int sub = t & 1;
    bool valid = v < n;
    int vv = valid ? v : 0;
    int b = blockIdx.y;
    int vbase = b * n;

    const float4* __restrict__ pk = g_pack;
    float4 p1 = pk[2 * (vbase + vv) + 0];
    float4 p2 = pk[2 * (vbase + vv) + 1];

    int start = accN[vv];
    int cnt = valid ? numN[vv] : 0;

    float S00 = 0.f, S01 = 0.f, S02 = 0.f;
    float S10 = 0.f, S11 = 0.f, S12 = 0.f;
    float S20 = 0.f, S21 = 0.f, S22 = 0.f;

    auto accum = [&](float4 q1, float4 q2, float wv) {
        float d1x = p1.x - q1.x, d1y = p1.y - q1.y, d1z = p1.z - q1.z;
        float d2x = p2.x - q2.x, d2y = p2.y - q2.y, d2z = p2.z - q2.z;
        float wx = wv * d1x, wy = wv * d1y, wz = wv * d1z;
        S00 = fmaf(wx, d2x, S00); S01 = fmaf(wx, d2y, S01); S02 = fmaf(wx, d2z, S02);
        S10 = fmaf(wy, d2x, S10); S11 = fmaf(wy, d2y, S11); S12 = fmaf(wy, d2z, S12);
        S20 = fmaf(wz, d2x, S20); S21 = fmaf(wz, d2y, S21); S22 = fmaf(wz, d2z, S22);
    };

    if (cnt == 16 && (start & 3) == 0) {
        int s8 = start + sub * 8;
        int4 na = *(const int4*)(nbr + s8);
        int4 nb = *(const int4*)(nbr + s8 + 4);
        float4 wa = *(const float4*)(wgt + s8);
        float4 wb = *(const float4*)(wgt + s8 + 4);
        // Front-batch all 16 coordinate gathers (MLP=16 per thread).
        float4 q0a = pk[2 * (vbase + na.x) + 0];
        float4 q0b = pk[2 * (vbase + na.x) + 1];
        float4 q1a = pk[2 * (vbase + na.y) + 0];
        float4 q1b = pk[2 * (vbase + na.y) + 1];
        float4 q2a = pk[2 * (vbase + na.z) + 0];
        float4 q2b = pk[2 * (vbase + na.z) + 1];
        float4 q3a = pk[2 * (vbase + na.w) + 0];
        float4 q3b = pk[2 * (vbase + na.w) + 1];
        float4 q4a = pk[2 * (vbase + nb.x) + 0];
        float4 q4b = pk[2 * (vbase + nb.x) + 1];
        float4 q5a = pk[2 * (vbase + nb.y) + 0];
        float4 q5b = pk[2 * (vbase + nb.y) + 1];
        float4 q6a = pk[2 * (vbase + nb.z) + 0];
        float4 q6b = pk[2 * (vbase + nb.z) + 1];
        float4 q7a = pk[2 * (vbase + nb.w) + 0];
        float4 q7b = pk[2 * (vbase + nb.w) + 1];
        accum(q0a, q0b, wa.x);
        accum(q1a, q1b, wa.y);
        accum(q2a, q2b, wa.z);
        accum(q3a, q3b, wa.w);
        accum(q4a, q4b, wb.x);
        accum(q5a, q5b, wb.y);
        accum(q6a, q6b, wb.z);
        accum(q7a, q7b, wb.w);
    } else {
        for (int k = sub; k < cnt; k += 2) {
            int j = nbr[start + k];
            accum(pk[2 * (vbase + j) + 0], pk[2 * (vbase + j) + 1], wgt[start + k]);
        }
    }

    // One-hop butterfly: both lanes of the pair end with the full sums.
#define RED2(x) x += __shfl_xor_sync(0xffffffffu, x, 1);
    RED2(S00) RED2(S01) RED2(S02)
    RED2(S10) RED2(S11) RED2(S12)
    RED2(S20) RED2(S21) RED2(S22)
#undef RED2

    // ---- Procrustes solve (redundant in both lanes; 2x issue only) ----
    float K[3][3];
    K[0][0] = S00 * S00 + S10 * S10 + S20 * S20;
    K[0][1] = S00 * S01 + S10 * S11 + S20 * S21;
    K[0][2] = S00 * S02 + S10 * S12 + S20 * S22;
    K[1][1] = S01 * S01 + S11 * S11 + S21 * S21;
    K[1][2] = S01 * S02 + S11 * S12 + S21 * S22;
    K[2][2] = S02 * S02 + S12 * S12 + S22 * S22;
    K[1][0] = K[0][1]; K[2][0] = K[0][2]; K[2][1] = K[1][2];

    float V[3][3] = {{1.f, 0.f, 0.f}, {0.f, 1.f, 0.f}, {0.f, 0.f, 1.f}};
#pragma unroll
    for (int sweep = 0; sweep < 4; sweep++) {
        jrot<0, 1>(K, V);
        jrot<1, 2>(K, V);
        jrot<0, 2>(K, V);
    }

    // Sort eigenpairs descending.
    float l0 = K[0][0], l1 = K[1][1], l2 = K[2][2], tt;
    if (l0 < l1) {
        tt = l0; l0 = l1; l1 = tt;
        tt = V[0][0]; V[0][0] = V[0][1]; V[0][1] = tt;
        tt = V[1][0]; V[1][0] = V[1][1]; V[1][1] = tt;
        tt = V[2][0]; V[2][0] = V[2][1]; V[2][1] = tt;
    }
    if (l0 < l2) {
        tt = l0; l0 = l2; l2 = tt;
        tt = V[0][0]; V[0][0] = V[0][2]; V[0][2] = tt;
        tt = V[1][0]; V[1][0] = V[1][2]; V[1][2] = tt;
        tt = V[2][0]; V[2][0] = V[2][2]; V[2][2] = tt;
    }
    if (l1 < l2) {
        tt = l1; l1 = l2; l2 = tt;
        tt = V[0][1]; V[0][1] = V[0][2]; V[0][2] = tt;
        tt = V[1][1]; V[1][1] = V[1][2]; V[1][2] = tt;
        tt = V[2][1]; V[2][1] = V[2][2]; V[2][2] = tt;
    }

    // Force det(V) = +1.
    {
        float cx = V[1][1] * V[2][2] - V[2][1] * V[1][2];
        float cy = V[2][1] * V[0][2] - V[0][1] * V[2][2];
        float cz = V[0][1] * V[1][2] - V[1][1] * V[0][2];
        float det = V[0][0] * cx + V[1][0] * cy + V[2][0] * cz;
        if (det < 0.f) { V[0][2] = -V[0][2]; V[1][2] = -V[1][2]; V[2][2] = -V[2][2]; }
    }

    // u0 = S v0 / |S v0|, u1 = S v1 / |S v1|, u2 = u0 x u1 (det(U)=+1: the
    // reference's reflection fix lands on the smallest singular direction).
    float b0x = S00 * V[0][0] + S01 * V[1][0] + S02 * V[2][0];
    float b0y = S10 * V[0][0] + S11 * V[1][0] + S12 * V[2][0];
    float b0z = S20 * V[0][0] + S21 * V[1][0] + S22 * V[2][0];
    float b1x = S00 * V[0][1] + S01 * V[1][1] + S02 * V[2][1];
    float b1y = S10 * V[0][1] + S11 * V[1][1] + S12 * V[2][1];
    float b1z = S20 * V[0][1] + S21 * V[1][1] + S22 * V[2][1];

    float r0 = frsqrt_fast(b0x * b0x + b0y * b0y + b0z * b0z);
    float u0x = b0x * r0, u0y = b0y * r0, u0z = b0z * r0;
    float r1 = frsqrt_fast(b1x * b1x + b1y * b1y + b1z * b1z);
    float u1x = b1x * r1, u1y = b1y * r1, u1z = b1z * r1;
    float u2x = u0y * u1z - u0z * u1y;
    float u2y = u0z * u1x - u0x * u1z;
    float u2z = u0x * u1y - u0y * u1x;

    // R = V U^T: compute all 9 entries in both lanes, split the store.
    float R0 = V[0][0] * u0x + V[0][1] * u1x + V[0][2] * u2x;
    float R1 = V[0][0] * u0y + V[0][1] * u1y + V[0][2] * u2y;
    float R2 = V[0][0] * u0z + V[0][1] * u1z + V[0][2] * u2z;
    float R3 = V[1][0] * u0x + V[1][1] * u1x + V[1][2] * u2x;
    float R4 = V[1][0] * u0y + V[1][1] * u1y + V[1][2] * u2y;
    float R5 = V[1][0] * u0z + V[1][1] * u1z + V[1][2] * u2z;
    float R6 = V[2][0] * u0x + V[2][1] * u1x + V[2][2] * u2x;
    float R7 = V[2][0] * u0y + V[2][1] * u1y + V[2][2] * u2y;
    float R8 = V[2][0] * u0z + V[2][1] * u1z + V[2][2] * u2z;

    if (valid) {
        float* o = out + (size_t)(vbase + vv) * 9;
        if (sub == 0) {
            o[0] = R0; o[1] = R1; o[2] = R2; o[3] = R3; o[4] = R4;
        } else {
            o[5] = R5; o[6] = R6; o[7] = R7; o[8] = R8;
        }
    }
}

// ---------------------------------------------------------------------------
// Inputs: xyz1, xyz2, neighborList, numNeighbors, accnumNeighbors,
// weightMatrix, rotations, arapWeight
// ---------------------------------------------------------------------------
extern "C" void kernel_launch(void* const* d_in, const int* in_sizes, int n_in,
                              void* d_out, int out_size) {
    const float* xyz1 = (const float*)d_in[0];
    const float* xyz2 = (const float*)d_in[1];
    const int* nbr = (const int*)d_in[2];
    const int* numN = (const int*)d_in[3];
    const int* accN = (const int*)d_in[4];
    const float* wgt = (const float*)d_in[5];
    float* out = (float*)d_out;

    int n = in_sizes[3];            // N vertices
    int b = in_sizes[0] / (3 * n);  // batches
    int npts = b * n;

    pack_kernel<<<(npts + 255) / 256, 256>>>(xyz1, xyz2, npts);

    dim3 grid((n * 2 + 255) / 256, b);
    arap_fused_kernel<<<grid, 256>>>(nbr, numN, accN, wgt, out, n);
}

// round 12
// speedup vs baseline: 1.4542x; 1.4542x over previous
#include <cuda_runtime.h>
#include <cstddef>

// Problem constants (dataset: B=2, N=50000, D=16)
#define MAXB 2
#define MAXN 50000

// Packed coordinates: g_pack[2t] = {x1,y1,z1,0}, g_pack[2t+1] = {x2,y2,z2,0}.
// 32B-aligned pair -> both float4 gathers for one neighbor hit ONE 32B sector.
__device__ float4 g_pack[2 * MAXB * MAXN];

// FMA-pipe inverse sqrt (no MUFU). 2 Newton steps: rel err ~5e-6.
__device__ __forceinline__ float frsqrt_fast(float x) {
    float xh = 0.5f * x;
    float y = __int_as_float(0x5f3759df - (__float_as_int(x) >> 1));
    y = y * (1.5f - xh * y * y);
    y = y * (1.5f - xh * y * y);
    return y;
}

// ---------------------------------------------------------------------------
// Kernel 1: float3 AoS -> interleaved float4 pairs.
// Thread t = point t: lane-stride-3 scalar loads (coalesced), 32B float4
// stores. Measured ~1.7us in R2 — keep exactly this shape.
// ---------------------------------------------------------------------------
__global__ void pack_kernel(const float* __restrict__ xyz1,
                            const float* __restrict__ xyz2, int npts) {
    int t = blockIdx.x * blockDim.x + threadIdx.x;
    if (t >= npts) return;
    float ax = xyz1[3 * t + 0], ay = xyz1[3 * t + 1], az = xyz1[3 * t + 2];
    float cx = xyz2[3 * t + 0], cy = xyz2[3 * t + 1], cz = xyz2[3 * t + 2];
    g_pack[2 * t + 0] = make_float4(ax, ay, az, 0.f);
    g_pack[2 * t + 1] = make_float4(cx, cy, cz, 0.f);
}

// ---------------------------------------------------------------------------
// Exact Givens Jacobi rotation (FMA-pipe only): zeroes K[p][q].
// ---------------------------------------------------------------------------
template <int p, int q>
__device__ __forceinline__ void jrot(float K[3][3], float V[3][3]) {
    constexpr int r3 = 3 - p - q;
    float apq = K[p][q];
    float ad = K[p][p] - K[q][q];
    float b2 = 2.f * apq;
    float rsq = fmaf(ad, ad, b2 * b2) + 1e-30f;
    float w = frsqrt_fast(rsq);
    float r = rsq * w;  // sqrt(rsq)
    float u = r + fabsf(ad);
    float kk = frsqrt_fast(2.f * r * u);
    float c0 = u * kk;
    float s0 = b2 * kk;
    float c, s;
    if (ad >= 0.f) { c = c0; s = s0; }
    else           { c = fabsf(s0); s = copysignf(c0, b2); }

    float kpp = K[p][p], kqq = K[q][q], kpr = K[p][r3], kqr = K[q][r3];
    float cc = c * c, ss = s * s, cs = c * s;
    K[p][p] = cc * kpp + 2.f * cs * apq + ss * kqq;
    K[q][q] = ss * kpp - 2.f * cs * apq + cc * kqq;
    float npq = cs * (kqq - kpp) + (cc - ss) * apq;
    K[p][q] = npq; K[q][p] = npq;
    float npr = fmaf(c, kpr, s * kqr);
    float nqr = fmaf(-s, kpr, c * kqr);
    K[p][r3] = npr; K[r3][p] = npr;
    K[q][r3] = nqr; K[r3][q] = nqr;

#pragma unroll
    for (int i2 = 0; i2 < 3; i2++) {
        float vp = V[i2][p], vq = V[i2][q];
        V[i2][p] = fmaf(c, vp, s * vq);
        V[i2][q] = fmaf(-s, vp, c * vq);
    }
}

// ---------------------------------------------------------------------------
// Kernel 2 (fused): ONE thread per (batch, vertex).
// Gather in 4 waves of 4 neighbors: 8 float4 loads front-batched per wave
// (32 data regs in flight -> fits the ~85-reg budget so ptxas keeps MLP=8),
// __launch_bounds__(256,3) -> 3 blocks/SM = 24 warps (37.5% occ).
// ---------------------------------------------------------------------------
__global__ __launch_bounds__(256, 3) void arap_fused_kernel(
    const int* __restrict__ nbr, const int* __restrict__ numN,
    const int* __restrict__ accN, const float* __restrict__ wgt,
    float* __restrict__ out, int n) {
    int i = blockIdx.x * blockDim.x + threadIdx.x;
    int b = blockIdx.y;
    if (i >= n) return;
    int vbase = b * n;

    // Issue CSR metadata loads first so the wave-0 index load overlaps the
    // point-pair loads instead of serializing behind them.
    int start = accN[i];
    int cnt = numN[i];

    const float4* __restrict__ pk = g_pack;
    float4 p1 = pk[2 * (vbase + i) + 0];
    float4 p2 = pk[2 * (vbase + i) + 1];

    float S00 = 0.f, S01 = 0.f, S02 = 0.f;
    float S10 = 0.f, S11 = 0.f, S12 = 0.f;
    float S20 = 0.f, S21 = 0.f, S22 = 0.f;

    auto accum = [&](float4 q1, float4 q2, float wv) {
        float d1x = p1.x - q1.x, d1y = p1.y - q1.y, d1z = p1.z - q1.z;
        float d2x = p2.x - q2.x, d2y = p2.y - q2.y, d2z = p2.z - q2.z;
        float wx = wv * d1x, wy = wv * d1y, wz = wv * d1z;
        S00 = fmaf(wx, d2x, S00); S01 = fmaf(wx, d2y, S01); S02 = fmaf(wx, d2z, S02);
        S10 = fmaf(wy, d2x, S10); S11 = fmaf(wy, d2y, S11); S12 = fmaf(wy, d2z, S12);
        S20 = fmaf(wz, d2x, S20); S21 = fmaf(wz, d2y, S21); S22 = fmaf(wz, d2z, S22);
    };

    if (cnt == 16 && (start & 3) == 0) {
        const int4* n4 = (const int4*)(nbr + start);
        const float4* w4 = (const float4*)(wgt + start);
#pragma unroll
        for (int wave = 0; wave < 4; wave++) {
            int4 nn = n4[wave];
            float4 ww = w4[wave];
            // Front-batch 8 coordinate gathers (MLP=8, 32 regs in flight).
            float4 a1 = pk[2 * (vbase + nn.x) + 0];
            float4 a2 = pk[2 * (vbase + nn.x) + 1];
            float4 b1 = pk[2 * (vbase + nn.y) + 0];
            float4 b2 = pk[2 * (vbase + nn.y) + 1];
            float4 c1 = pk[2 * (vbase + nn.z) + 0];
            float4 c2 = pk[2 * (vbase + nn.z) + 1];
            float4 d1 = pk[2 * (vbase + nn.w) + 0];
            float4 d2 = pk[2 * (vbase + nn.w) + 1];
            accum(a1, a2, ww.x);
            accum(b1, b2, ww.y);
            accum(c1, c2, ww.z);
            accum(d1, d2, ww.w);
        }
    } else {
        for (int k = 0; k < cnt; k++) {
            int j = nbr[start + k];
            accum(pk[2 * (vbase + j) + 0], pk[2 * (vbase + j) + 1], wgt[start + k]);
        }
    }

    // ---- Procrustes solve ----
    float K[3][3];
    K[0][0] = S00 * S00 + S10 * S10 + S20 * S20;
    K[0][1] = S00 * S01 + S10 * S11 + S20 * S21;
    K[0][2] = S00 * S02 + S10 * S12 + S20 * S22;
    K[1][1] = S01 * S01 + S11 * S11 + S21 * S21;
    K[1][2] = S01 * S02 + S11 * S12 + S21 * S22;
    K[2][2] = S02 * S02 + S12 * S12 + S22 * S22;
    K[1][0] = K[0][1]; K[2][0] = K[0][2]; K[2][1] = K[1][2];

    float V[3][3] = {{1.f, 0.f, 0.f}, {0.f, 1.f, 0.f}, {0.f, 0.f, 1.f}};
#pragma unroll
    for (int sweep = 0; sweep < 4; sweep++) {
        jrot<0, 1>(K, V);
        jrot<1, 2>(K, V);
        jrot<0, 2>(K, V);
    }

    // Sort eigenpairs descending.
    float l0 = K[0][0], l1 = K[1][1], l2 = K[2][2], tt;
    if (l0 < l1) {
        tt = l0; l0 = l1; l1 = tt;
        tt = V[0][0]; V[0][0] = V[0][1]; V[0][1] = tt;
        tt = V[1][0]; V[1][0] = V[1][1]; V[1][1] = tt;
        tt = V[2][0]; V[2][0] = V[2][1]; V[2][1] = tt;
    }
    if (l0 < l2) {
        tt = l0; l0 = l2; l2 = tt;
        tt = V[0][0]; V[0][0] = V[0][2]; V[0][2] = tt;
        tt = V[1][0]; V[1][0] = V[1][2]; V[1][2] = tt;
        tt = V[2][0]; V[2][0] = V[2][2]; V[2][2] = tt;
    }
    if (l1 < l2) {
        tt = l1; l1 = l2; l2 = tt;
        tt = V[0][1]; V[0][1] = V[0][2]; V[0][2] = tt;
        tt = V[1][1]; V[1][1] = V[1][2]; V[1][2] = tt;
        tt = V[2][1]; V[2][1] = V[2][2]; V[2][2] = tt;
    }

    // Force det(V) = +1.
    {
        float cx = V[1][1] * V[2][2] - V[2][1] * V[1][2];
        float cy = V[2][1] * V[0][2] - V[0][1] * V[2][2];
        float cz = V[0][1] * V[1][2] - V[1][1] * V[0][2];
        float det = V[0][0] * cx + V[1][0] * cy + V[2][0] * cz;
        if (det < 0.f) { V[0][2] = -V[0][2]; V[1][2] = -V[1][2]; V[2][2] = -V[2][2]; }
    }

    // u0 = S v0 / |S v0|, u1 = S v1 / |S v1|, u2 = u0 x u1 (det(U)=+1: the
    // reference's reflection fix lands on the smallest singular direction).
    float b0x = S00 * V[0][0] + S01 * V[1][0] + S02 * V[2][0];
    float b0y = S10 * V[0][0] + S11 * V[1][0] + S12 * V[2][0];
    float b0z = S20 * V[0][0] + S21 * V[1][0] + S22 * V[2][0];
    float b1x = S00 * V[0][1] + S01 * V[1][1] + S02 * V[2][1];
    float b1y = S10 * V[0][1] + S11 * V[1][1] + S12 * V[2][1];
    float b1z = S20 * V[0][1] + S21 * V[1][1] + S22 * V[2][1];

    float r0 = frsqrt_fast(b0x * b0x + b0y * b0y + b0z * b0z);
    float u0x = b0x * r0, u0y = b0y * r0, u0z = b0z * r0;
    float r1 = frsqrt_fast(b1x * b1x + b1y * b1y + b1z * b1z);
    float u1x = b1x * r1, u1y = b1y * r1, u1z = b1z * r1;
    float u2x = u0y * u1z - u0z * u1y;
    float u2y = u0z * u1x - u0x * u1z;
    float u2z = u0x * u1y - u0y * u1x;

    // R = V U^T, row-major
    float* o = out + (size_t)(vbase + i) * 9;
    o[0] = V[0][0] * u0x + V[0][1] * u1x + V[0][2] * u2x;
    o[1] = V[0][0] * u0y + V[0][1] * u1y + V[0][2] * u2y;
    o[2] = V[0][0] * u0z + V[0][1] * u1z + V[0][2] * u2z;
    o[3] = V[1][0] * u0x + V[1][1] * u1x + V[1][2] * u2x;
    o[4] = V[1][0] * u0y + V[1][1] * u1y + V[1][2] * u2y;
    o[5] = V[1][0] * u0z + V[1][1] * u1z + V[1][2] * u2z;
    o[6] = V[2][0] * u0x + V[2][1] * u1x + V[2][2] * u2x;
    o[7] = V[2][0] * u0y + V[2][1] * u1y + V[2][2] * u2y;
    o[8] = V[2][0] * u0z + V[2][1] * u1z + V[2][2] * u2z;
}

// ---------------------------------------------------------------------------
// Inputs: xyz1, xyz2, neighborList, numNeighbors, accnumNeighbors,
// weightMatrix, rotations, arapWeight
// ---------------------------------------------------------------------------
extern "C" void kernel_launch(void* const* d_in, const int* in_sizes, int n_in,
                              void* d_out, int out_size) {
    const float* xyz1 = (const float*)d_in[0];
    const float* xyz2 = (const float*)d_in[1];
    const int* nbr = (const int*)d_in[2];
    const int* numN = (const int*)d_in[3];
    const int* accN = (const int*)d_in[4];
    const float* wgt = (const float*)d_in[5];
    float* out = (float*)d_out;

    int n = in_sizes[3];            // N vertices
    int b = in_sizes[0] / (3 * n);  // batches
    int npts = b * n;

    pack_kernel<<<(npts + 255) / 256, 256>>>(xyz1, xyz2, npts);

    dim3 grid((n + 255) / 256, b);
    arap_fused_kernel<<<grid, 256>>>(nbr, numN, accN, wgt, out, n);
}